// round 7
// baseline (speedup 1.0000x reference)
#include <cuda_runtime.h>
#include <cstdint>

// ---------------------------------------------------------------------------
// ExpertGather: y[b,e,k,j] = sum_i x[b, Ind[b,e,k], i] * W[e,i,j]
// B=8, T=2048, I=1024, E=16, K=256, J=1024.  fp32 in/out.
// Legacy mma.sync m16n8k8 tf32 (harness targets sm_100: no tcgen05).
// CTA 128x128, 4 warps of 64x64 (halves fragment-read traffic vs 64x32),
// 3-stage cp.async pipeline (no register-staged STS), cvt.rna on fragment load.
// ---------------------------------------------------------------------------

#define BB 8
#define TT 2048
#define II 1024
#define EE 16
#define KG 256
#define JJ 1024

#define TM 128
#define TN 128
#define TK 32
#define THREADS 128
#define STAGES 3

#define AST 36                      // A row stride in floats (32 + 4 pad)
#define BST 132                     // B row stride in floats (128 + 4 pad)
#define A_STG (TM * AST)            // 4608 floats
#define B_STG (TK * BST)            // 4224 floats
#define STG_FLOATS (A_STG + B_STG)  // 8832 floats
#define SM_BYTES (STAGES * STG_FLOATS * 4)   // 105984 B

__device__ __forceinline__ uint32_t smem_u32(const void* p) {
    uint32_t a;
    asm("{ .reg .u64 t; cvta.to.shared.u64 t, %1; cvt.u32.u64 %0, t; }"
        : "=r"(a) : "l"(p));
    return a;
}

__device__ __forceinline__ uint32_t f2tf(float f) {
    uint32_t u;
    asm("cvt.rna.tf32.f32 %0, %1;" : "=r"(u) : "f"(f));
    return u;
}

__device__ __forceinline__ void cp16(uint32_t dst, const void* src) {
    asm volatile("cp.async.cg.shared.global [%0], [%1], 16;"
                 :: "r"(dst), "l"(src) : "memory");
}

__device__ __forceinline__ void mma_tf32(float* c, const uint32_t* a,
                                         const uint32_t* b) {
    asm volatile(
        "mma.sync.aligned.m16n8k8.row.col.f32.tf32.tf32.f32 "
        "{%0,%1,%2,%3}, {%4,%5,%6,%7}, {%8,%9}, {%0,%1,%2,%3};"
        : "+f"(c[0]), "+f"(c[1]), "+f"(c[2]), "+f"(c[3])
        : "r"(a[0]), "r"(a[1]), "r"(a[2]), "r"(a[3]),
          "r"(b[0]), "r"(b[1]));
}

__global__ void __launch_bounds__(THREADS)
eg_kernel(const float* __restrict__ x, const float* __restrict__ W,
          const void* __restrict__ IndRaw, float* __restrict__ out)
{
    extern __shared__ __align__(16) float sm[];
    const uint32_t sbase = smem_u32(sm);

    const int tid  = threadIdx.x;
    const int wid  = tid >> 5;
    const int lane = tid & 31;
    const int g    = lane >> 2;     // 0..7
    const int tig  = lane & 3;      // 0..3
    const int warpM = wid >> 1;     // 0..1
    const int warpN = wid & 1;      // 0..1

    const int bid = blockIdx.x;
    const int nt = bid & 7;
    const int mt = (bid >> 3) & 1;
    const int e  = (bid >> 4) & 15;
    const int b  = bid >> 8;
    const int m0 = mt * TM;
    const int n0 = nt * TN;

    // Ind dtype autodetect (declared int64; JAX w/o x64 emits int32).
    const int* ii = (const int*)IndRaw;
    const bool is64 = ((ii[1] | ii[3] | ii[5] | ii[7]) == 0);

    // One gathered row per thread (128 threads = 128 rows).
    const long long gidx = (long long)(b * EE + e) * KG + m0 + tid;
    long long t = is64 ? ((const long long*)IndRaw)[gidx] : (long long)ii[gidx];
    t &= (TT - 1);   // no OOB possible
    const float* arow = x + ((size_t)b * TT + (size_t)t) * II;
    const float* wb   = W + (size_t)e * II * JJ + n0;

    // ---- async load of chunk kc into stage s ----
    auto load_stage = [&](int kc, int s) {
        const uint32_t aB = sbase + (uint32_t)(s * STG_FLOATS * 4);
        const uint32_t bB = aB + A_STG * 4;
        const char* ap = (const char*)(arow + kc * TK);
        #pragma unroll
        for (int q = 0; q < 8; ++q)
            cp16(aB + (uint32_t)(tid * (AST * 4) + q * 16), ap + q * 16);
        #pragma unroll
        for (int it = 0; it < 8; ++it) {
            int idx = it * THREADS + tid;       // 0..1023
            int k   = idx >> 5;                 // 0..31
            int n4  = idx & 31;                 // 16B unit within 128 floats
            cp16(bB + (uint32_t)(k * (BST * 4) + n4 * 16),
                 wb + (size_t)(kc * TK + k) * JJ + (n4 << 2));
        }
    };

    float acc[4][8][4];
    #pragma unroll
    for (int mf = 0; mf < 4; ++mf)
        #pragma unroll
        for (int nf = 0; nf < 8; ++nf)
            #pragma unroll
            for (int c = 0; c < 4; ++c) acc[mf][nf][c] = 0.0f;

    // ---- compute one chunk from stage s ----
    auto compute = [&](int s) {
        const float* A = sm + s * STG_FLOATS;
        const float* B = A + A_STG;
        #pragma unroll
        for (int kk = 0; kk < 4; ++kk) {
            const int k = kk * 8 + tig;
            uint32_t af[4][4], bf[8][2];
            #pragma unroll
            for (int mf = 0; mf < 4; ++mf) {
                const int r = warpM * 64 + mf * 16 + g;
                af[mf][0] = f2tf(A[r * AST + k]);
                af[mf][1] = f2tf(A[(r + 8) * AST + k]);
                af[mf][2] = f2tf(A[r * AST + k + 4]);
                af[mf][3] = f2tf(A[(r + 8) * AST + k + 4]);
            }
            #pragma unroll
            for (int nf = 0; nf < 8; ++nf) {
                const int n = warpN * 64 + nf * 8 + g;
                bf[nf][0] = f2tf(B[k * BST + n]);
                bf[nf][1] = f2tf(B[(k + 4) * BST + n]);
            }
            #pragma unroll
            for (int mf = 0; mf < 4; ++mf)
                #pragma unroll
                for (int nf = 0; nf < 8; ++nf)
                    mma_tf32(acc[mf][nf], af[mf], bf[nf]);
        }
    };

    // ---- prologue: prefetch STAGES-1 chunks ----
    #pragma unroll
    for (int s = 0; s < STAGES - 1; ++s) {
        load_stage(s, s);
        asm volatile("cp.async.commit_group;" ::: "memory");
    }

    // ---- main loop ----
    #pragma unroll 1
    for (int kc = 0; kc < II / TK; ++kc) {
        asm volatile("cp.async.wait_group %0;" :: "n"(STAGES - 2) : "memory");
        __syncthreads();
        const int pf = kc + STAGES - 1;
        if (pf < II / TK) load_stage(pf, pf % STAGES);
        asm volatile("cp.async.commit_group;" ::: "memory");
        compute(kc % STAGES);
    }

    // ---- epilogue: direct float2 stores ----
    const size_t rowbase = (size_t)((b * EE + e) * KG + m0);
    #pragma unroll
    for (int mf = 0; mf < 4; ++mf) {
        const int r0 = warpM * 64 + mf * 16 + g;
        #pragma unroll
        for (int nf = 0; nf < 8; ++nf) {
            const int c = n0 + warpN * 64 + nf * 8 + 2 * tig;
            float* p = out + (rowbase + r0) * JJ + c;
            *(float2*)p            = make_float2(acc[mf][nf][0], acc[mf][nf][1]);
            *(float2*)(p + 8 * JJ) = make_float2(acc[mf][nf][2], acc[mf][nf][3]);
        }
    }
}

extern "C" void kernel_launch(void* const* d_in, const int* in_sizes, int n_in,
                              void* d_out, int out_size) {
    const float* x   = (const float*)d_in[0];
    const float* W   = (const float*)d_in[1];
    const void*  Ind = d_in[2];
    float*       out = (float*)d_out;

    cudaFuncSetAttribute(eg_kernel, cudaFuncAttributeMaxDynamicSharedMemorySize,
                         SM_BYTES);

    const int grid = BB * EE * (KG / TM) * (JJ / TN);  // 8*16*2*8 = 2048
    eg_kernel<<<grid, THREADS, SM_BYTES>>>(x, W, Ind, out);
}